// round 8
// baseline (speedup 1.0000x reference)
#include <cuda_runtime.h>
#include <math.h>

// Problem constants
#define NB 8
#define SS 4096          // H*W
#define CC 512
#define EPS 1e-3

// ---------------- scratch (device globals; no allocation allowed) ----------
__device__ double g_sum[NB * CC];
__device__ double g_sumsq[NB * CC];
__device__ float  g_mean[NB * CC];
__device__ float  g_rstd[NB * CC];
__device__ float g_xn[(size_t)NB * SS * CC];    // 64 MB
__device__ float g_q [(size_t)NB * SS * CC];
__device__ float g_k [(size_t)NB * SS * CC];
__device__ float g_v [(size_t)NB * SS * CC];
__device__ float g_p [(size_t)NB * SS * CC];
__device__ float g_attn[(size_t)NB * SS * SS];  // 512 MB

// ---------------- stats (fp64 accumulation) --------------------------------
__global__ void zero_stats_kernel() {
    int i = blockIdx.x * blockDim.x + threadIdx.x;
    if (i < NB * CC) { g_sum[i] = 0.0; g_sumsq[i] = 0.0; }
}

// grid (NB, 32), block 512: thread t = channel t, each block covers 128 rows
__global__ void stats_kernel(const float* __restrict__ x) {
    const int ROWS = SS / 32;
    int b = blockIdx.x, chunk = blockIdx.y, c = threadIdx.x;
    const float* xp = x + ((size_t)b * SS + (size_t)chunk * ROWS) * CC + c;
    double s = 0.0, s2 = 0.0;
    #pragma unroll 4
    for (int i = 0; i < ROWS; ++i) {
        double v = (double)xp[(size_t)i * CC];
        s += v; s2 += v * v;
    }
    atomicAdd(&g_sum[b * CC + c], s);
    atomicAdd(&g_sumsq[b * CC + c], s2);
}

__global__ void finalize_stats_kernel() {
    int i = blockIdx.x * blockDim.x + threadIdx.x;
    if (i < NB * CC) {
        double mean = g_sum[i] * (1.0 / SS);
        double var  = g_sumsq[i] * (1.0 / SS) - mean * mean;
        if (var < 0.0) var = 0.0;
        g_mean[i] = (float)mean;
        g_rstd[i] = (float)(1.0 / sqrt(var + EPS));
    }
}

// xn = (x-mean)*rstd*gamma + beta ; write to g_xn (via symbol) and d_out
__global__ void norm_kernel(const float* __restrict__ x,
                            const float* __restrict__ gamma,
                            const float* __restrict__ beta,
                            float* __restrict__ xn_out,
                            float* __restrict__ out) {
    size_t i4 = (size_t)blockIdx.x * blockDim.x + threadIdx.x;
    size_t e = i4 * 4;
    if (e >= (size_t)NB * SS * CC) return;
    int c = (int)(e % CC);
    int b = (int)(e / ((size_t)SS * CC));
    float4 xv = *(const float4*)(x + e);
    float4 y;
    int base = b * CC + c;
    y.x = (xv.x - g_mean[base+0]) * g_rstd[base+0] * gamma[c+0] + beta[c+0];
    y.y = (xv.y - g_mean[base+1]) * g_rstd[base+1] * gamma[c+1] + beta[c+1];
    y.z = (xv.z - g_mean[base+2]) * g_rstd[base+2] * gamma[c+2] + beta[c+2];
    y.w = (xv.w - g_mean[base+3]) * g_rstd[base+3] * gamma[c+3] + beta[c+3];
    *(float4*)(xn_out + e) = y;
    *(float4*)(out + e)    = y;
}

// ---------------- SGEMM (128x128x8 tile, 8x8 per thread) -------------------
// NN: C[M,N] = alpha * A[M,K](row) * B[K,N](row) [+ bias] [+ C]
__global__ void __launch_bounds__(256)
sgemm_nn(const float* __restrict__ A, const float* __restrict__ Bm,
         const float* __restrict__ bias, float* __restrict__ Cm,
         int M, int N, int K,
         size_t strideA, size_t strideB, size_t strideC,
         float alpha, int accum) {
    const int BM = 128, BN = 128, BK = 8;
    __shared__ float As[BK][BM];
    __shared__ float Bs[BK][BN];
    A  += (size_t)blockIdx.z * strideA;
    Bm += (size_t)blockIdx.z * strideB;
    Cm += (size_t)blockIdx.z * strideC;
    int bm = blockIdx.y * BM, bn = blockIdx.x * BN;
    int tid = threadIdx.x;

    const int am = tid >> 1, ak = (tid & 1) * 4;     // A tile load: 128 rows x 8
    const int bk = tid >> 5, bn4 = (tid & 31) * 4;   // B tile load: 8 rows x 128
    const float* Aptr = A  + (size_t)(bm + am) * K + ak;
    const float* Bptr = Bm + (size_t)bk * N + bn + bn4;

    const int rowBase = (tid >> 4) * 8;
    const int colBase = (tid & 15) * 8;

    float acc[8][8];
    #pragma unroll
    for (int i = 0; i < 8; i++)
        #pragma unroll
        for (int j = 0; j < 8; j++) acc[i][j] = 0.f;

    for (int k0 = 0; k0 < K; k0 += BK) {
        float4 a = *(const float4*)Aptr;
        float4 b = *(const float4*)Bptr;
        As[ak+0][am] = a.x; As[ak+1][am] = a.y; As[ak+2][am] = a.z; As[ak+3][am] = a.w;
        *(float4*)&Bs[bk][bn4] = b;
        __syncthreads();
        #pragma unroll
        for (int kk = 0; kk < BK; ++kk) {
            float ar[8], br[8];
            #pragma unroll
            for (int i = 0; i < 8; i++) ar[i] = As[kk][rowBase + i];
            #pragma unroll
            for (int j = 0; j < 8; j++) br[j] = Bs[kk][colBase + j];
            #pragma unroll
            for (int i = 0; i < 8; i++)
                #pragma unroll
                for (int j = 0; j < 8; j++)
                    acc[i][j] = fmaf(ar[i], br[j], acc[i][j]);
        }
        __syncthreads();
        Aptr += BK;
        Bptr += (size_t)BK * N;
    }

    #pragma unroll
    for (int i = 0; i < 8; i++) {
        size_t row = (size_t)(bm + rowBase + i) * N + bn + colBase;
        #pragma unroll
        for (int j = 0; j < 8; j++) {
            float val = acc[i][j] * alpha;
            if (bias) val += bias[bn + colBase + j];
            if (accum) val += Cm[row + j];
            Cm[row + j] = val;
        }
    }
}

// NT: C[M,N] = alpha * A[M,K](row) * B[N,K](row)^T
__global__ void __launch_bounds__(256)
sgemm_nt(const float* __restrict__ A, const float* __restrict__ Bm,
         float* __restrict__ Cm,
         int M, int N, int K,
         size_t strideA, size_t strideB, size_t strideC,
         float alpha) {
    const int BM = 128, BN = 128, BK = 8;
    __shared__ float As[BK][BM];
    __shared__ float Bs[BK][BN];
    A  += (size_t)blockIdx.z * strideA;
    Bm += (size_t)blockIdx.z * strideB;
    Cm += (size_t)blockIdx.z * strideC;
    int bm = blockIdx.y * BM, bn = blockIdx.x * BN;
    int tid = threadIdx.x;

    const int am = tid >> 1, ak = (tid & 1) * 4;
    const float* Aptr = A  + (size_t)(bm + am) * K + ak;
    const float* Bptr = Bm + (size_t)(bn + am) * K + ak;

    const int rowBase = (tid >> 4) * 8;
    const int colBase = (tid & 15) * 8;

    float acc[8][8];
    #pragma unroll
    for (int i = 0; i < 8; i++)
        #pragma unroll
        for (int j = 0; j < 8; j++) acc[i][j] = 0.f;

    for (int k0 = 0; k0 < K; k0 += BK) {
        float4 a = *(const float4*)Aptr;
        float4 b = *(const float4*)Bptr;
        As[ak+0][am] = a.x; As[ak+1][am] = a.y; As[ak+2][am] = a.z; As[ak+3][am] = a.w;
        Bs[ak+0][am] = b.x; Bs[ak+1][am] = b.y; Bs[ak+2][am] = b.z; Bs[ak+3][am] = b.w;
        __syncthreads();
        #pragma unroll
        for (int kk = 0; kk < BK; ++kk) {
            float ar[8], br[8];
            #pragma unroll
            for (int i = 0; i < 8; i++) ar[i] = As[kk][rowBase + i];
            #pragma unroll
            for (int j = 0; j < 8; j++) br[j] = Bs[kk][colBase + j];
            #pragma unroll
            for (int i = 0; i < 8; i++)
                #pragma unroll
                for (int j = 0; j < 8; j++)
                    acc[i][j] = fmaf(ar[i], br[j], acc[i][j]);
        }
        __syncthreads();
        Aptr += BK;
        Bptr += BK;
    }

    #pragma unroll
    for (int i = 0; i < 8; i++) {
        size_t row = (size_t)(bm + rowBase + i) * N + bn + colBase;
        #pragma unroll
        for (int j = 0; j < 8; j++)
            Cm[row + j] = acc[i][j] * alpha;
    }
}

// ---------------- softmax (row-wise, 4096 per row) --------------------------
__global__ void __launch_bounds__(256)
softmax_kernel(float* __restrict__ attn) {
    float* row = attn + (size_t)blockIdx.x * SS;
    int t = threadIdx.x;
    __shared__ float sred[8];

    float v[16];
    float mx = -1e30f;
    #pragma unroll
    for (int i = 0; i < 16; i++) {
        v[i] = row[t + i * 256];
        mx = fmaxf(mx, v[i]);
    }
    #pragma unroll
    for (int o = 16; o > 0; o >>= 1) mx = fmaxf(mx, __shfl_xor_sync(0xffffffffu, mx, o));
    if ((t & 31) == 0) sred[t >> 5] = mx;
    __syncthreads();
    if (t == 0) {
        float m = sred[0];
        #pragma unroll
        for (int w = 1; w < 8; w++) m = fmaxf(m, sred[w]);
        sred[0] = m;
    }
    __syncthreads();
    mx = sred[0];
    __syncthreads();

    float sum = 0.f;
    #pragma unroll
    for (int i = 0; i < 16; i++) {
        v[i] = expf(v[i] - mx);
        sum += v[i];
    }
    #pragma unroll
    for (int o = 16; o > 0; o >>= 1) sum += __shfl_xor_sync(0xffffffffu, sum, o);
    if ((t & 31) == 0) sred[t >> 5] = sum;
    __syncthreads();
    if (t == 0) {
        float s = 0.f;
        #pragma unroll
        for (int w = 0; w < 8; w++) s += sred[w];
        sred[0] = s;
    }
    __syncthreads();
    float inv = 1.f / sred[0];

    #pragma unroll
    for (int i = 0; i < 16; i++)
        row[t + i * 256] = v[i] * inv;
}

// ---------------- launch -----------------------------------------------------
extern "C" void kernel_launch(void* const* d_in, const int* in_sizes, int n_in,
                              void* d_out, int out_size) {
    const float* x     = (const float*)d_in[0];
    const float* gamma = (const float*)d_in[1];
    const float* beta  = (const float*)d_in[2];
    const float* Wq    = (const float*)d_in[3];
    const float* bq    = (const float*)d_in[4];
    const float* Wk    = (const float*)d_in[5];
    const float* bk    = (const float*)d_in[6];
    const float* Wv    = (const float*)d_in[7];
    const float* bv    = (const float*)d_in[8];
    const float* Wp    = (const float*)d_in[9];
    const float* bp    = (const float*)d_in[10];
    float* out = (float*)d_out;

    // CRITICAL: resolve REAL device addresses of the __device__ scratch arrays.
    // Passing the symbols directly from host code passes the host shadow
    // address, which GB300's ATS happily dereferences (reading zeros from
    // host RAM) instead of faulting.
    float *p_xn, *p_q, *p_k, *p_v, *p_p, *p_attn;
    cudaGetSymbolAddress((void**)&p_xn,   g_xn);
    cudaGetSymbolAddress((void**)&p_q,    g_q);
    cudaGetSymbolAddress((void**)&p_k,    g_k);
    cudaGetSymbolAddress((void**)&p_v,    g_v);
    cudaGetSymbolAddress((void**)&p_p,    g_p);
    cudaGetSymbolAddress((void**)&p_attn, g_attn);

    const size_t SC  = (size_t)SS * CC;   // per-batch q/k/v stride
    const size_t SS2 = (size_t)SS * SS;   // per-batch attn stride
    const float scale = 0.044194173824159216f; // 512^-0.5

    // 1) instance-norm stats (fp64)
    zero_stats_kernel<<<(NB * CC + 511) / 512, 512>>>();
    stats_kernel<<<dim3(NB, 32), 512>>>(x);
    finalize_stats_kernel<<<(NB * CC + 511) / 512, 512>>>();

    // 2) normalize -> g_xn, and d_out (residual base)
    {
        size_t n4 = (size_t)NB * SS * CC / 4;
        norm_kernel<<<(unsigned)((n4 + 255) / 256), 256>>>(x, gamma, beta, p_xn, out);
    }

    // 3) q, k, v projections: [32768,512] @ [512,512] + bias
    {
        dim3 grid(CC / 128, (NB * SS) / 128, 1);
        sgemm_nn<<<grid, 256>>>(p_xn, Wq, bq, p_q, NB * SS, CC, CC, 0, 0, 0, 1.f, 0);
        sgemm_nn<<<grid, 256>>>(p_xn, Wk, bk, p_k, NB * SS, CC, CC, 0, 0, 0, 1.f, 0);
        sgemm_nn<<<grid, 256>>>(p_xn, Wv, bv, p_v, NB * SS, CC, CC, 0, 0, 0, 1.f, 0);
    }

    // 4) scores = scale * q @ k^T  (per batch, NT)
    {
        dim3 grid(SS / 128, SS / 128, NB);
        sgemm_nt<<<grid, 256>>>(p_q, p_k, p_attn, SS, SS, CC, SC, SC, SS2, scale);
    }

    // 5) softmax over last dim
    softmax_kernel<<<NB * SS, 256>>>(p_attn);

    // 6) proj = attn @ v (per batch, NN, K=4096)
    {
        dim3 grid(CC / 128, SS / 128, NB);
        sgemm_nn<<<grid, 256>>>(p_attn, p_v, nullptr, p_p, SS, CC, SS, SS2, SC, SC, 1.f, 0);
    }

    // 7) out = xn (already in d_out) + proj @ Wp + bp
    {
        dim3 grid(CC / 128, (NB * SS) / 128, 1);
        sgemm_nn<<<grid, 256>>>(p_p, Wp, bp, out, NB * SS, CC, CC, 0, 0, 0, 1.f, 1);
    }
}

// round 9
// speedup vs baseline: 1.0004x; 1.0004x over previous
#include <cuda_runtime.h>
#include <math.h>

// Problem constants
#define NB 8
#define SS 4096          // H*W
#define CC 512
#define EPS 1e-3

// ---------------- scratch (device globals; no allocation allowed) ----------
__device__ double g_sum[NB * CC];
__device__ double g_sumsq[NB * CC];
__device__ float  g_mean[NB * CC];
__device__ float  g_rstd[NB * CC];
__device__ float g_xn[(size_t)NB * SS * CC];    // 64 MB
__device__ float g_q [(size_t)NB * SS * CC];
__device__ float g_k [(size_t)NB * SS * CC];
__device__ float g_v [(size_t)NB * SS * CC];
__device__ float g_p [(size_t)NB * SS * CC];
__device__ float g_attn[(size_t)NB * SS * SS];  // 512 MB

// ---------------- stats (fp64 accumulation) --------------------------------
__global__ void zero_stats_kernel() {
    int i = blockIdx.x * blockDim.x + threadIdx.x;
    if (i < NB * CC) { g_sum[i] = 0.0; g_sumsq[i] = 0.0; }
}

// grid (NB, 32), block 512: thread t = channel t, each block covers 128 rows
__global__ void stats_kernel(const float* __restrict__ x) {
    const int ROWS = SS / 32;
    int b = blockIdx.x, chunk = blockIdx.y, c = threadIdx.x;
    const float* xp = x + ((size_t)b * SS + (size_t)chunk * ROWS) * CC + c;
    double s = 0.0, s2 = 0.0;
    #pragma unroll 4
    for (int i = 0; i < ROWS; ++i) {
        double v = (double)xp[(size_t)i * CC];
        s += v; s2 += v * v;
    }
    atomicAdd(&g_sum[b * CC + c], s);
    atomicAdd(&g_sumsq[b * CC + c], s2);
}

__global__ void finalize_stats_kernel() {
    int i = blockIdx.x * blockDim.x + threadIdx.x;
    if (i < NB * CC) {
        double mean = g_sum[i] * (1.0 / SS);
        double var  = g_sumsq[i] * (1.0 / SS) - mean * mean;
        if (var < 0.0) var = 0.0;
        g_mean[i] = (float)mean;
        g_rstd[i] = (float)(1.0 / sqrt(var + EPS));
    }
}

// xn = (x-mean)*rstd*gamma + beta ; write to g_xn (via symbol) and d_out
__global__ void norm_kernel(const float* __restrict__ x,
                            const float* __restrict__ gamma,
                            const float* __restrict__ beta,
                            float* __restrict__ xn_out,
                            float* __restrict__ out) {
    size_t i4 = (size_t)blockIdx.x * blockDim.x + threadIdx.x;
    size_t e = i4 * 4;
    if (e >= (size_t)NB * SS * CC) return;
    int c = (int)(e % CC);
    int b = (int)(e / ((size_t)SS * CC));
    float4 xv = *(const float4*)(x + e);
    float4 y;
    int base = b * CC + c;
    y.x = (xv.x - g_mean[base+0]) * g_rstd[base+0] * gamma[c+0] + beta[c+0];
    y.y = (xv.y - g_mean[base+1]) * g_rstd[base+1] * gamma[c+1] + beta[c+1];
    y.z = (xv.z - g_mean[base+2]) * g_rstd[base+2] * gamma[c+2] + beta[c+2];
    y.w = (xv.w - g_mean[base+3]) * g_rstd[base+3] * gamma[c+3] + beta[c+3];
    *(float4*)(xn_out + e) = y;
    *(float4*)(out + e)    = y;
}

// ---------------- SGEMM (128x128x8 tile, 8x8 per thread) -------------------
// NN: C[M,N] = alpha * A[M,K](row) * B[K,N](row) [+ bias] [+ C]
__global__ void __launch_bounds__(256)
sgemm_nn(const float* __restrict__ A, const float* __restrict__ Bm,
         const float* __restrict__ bias, float* __restrict__ Cm,
         int M, int N, int K,
         size_t strideA, size_t strideB, size_t strideC,
         float alpha, int accum) {
    const int BM = 128, BN = 128, BK = 8;
    __shared__ float As[BK][BM];
    __shared__ float Bs[BK][BN];
    A  += (size_t)blockIdx.z * strideA;
    Bm += (size_t)blockIdx.z * strideB;
    Cm += (size_t)blockIdx.z * strideC;
    int bm = blockIdx.y * BM, bn = blockIdx.x * BN;
    int tid = threadIdx.x;

    const int am = tid >> 1, ak = (tid & 1) * 4;     // A tile load: 128 rows x 8
    const int bk = tid >> 5, bn4 = (tid & 31) * 4;   // B tile load: 8 rows x 128
    const float* Aptr = A  + (size_t)(bm + am) * K + ak;
    const float* Bptr = Bm + (size_t)bk * N + bn + bn4;

    const int rowBase = (tid >> 4) * 8;
    const int colBase = (tid & 15) * 8;

    float acc[8][8];
    #pragma unroll
    for (int i = 0; i < 8; i++)
        #pragma unroll
        for (int j = 0; j < 8; j++) acc[i][j] = 0.f;

    for (int k0 = 0; k0 < K; k0 += BK) {
        float4 a = *(const float4*)Aptr;
        float4 b = *(const float4*)Bptr;
        As[ak+0][am] = a.x; As[ak+1][am] = a.y; As[ak+2][am] = a.z; As[ak+3][am] = a.w;
        *(float4*)&Bs[bk][bn4] = b;
        __syncthreads();
        #pragma unroll
        for (int kk = 0; kk < BK; ++kk) {
            float ar[8], br[8];
            #pragma unroll
            for (int i = 0; i < 8; i++) ar[i] = As[kk][rowBase + i];
            #pragma unroll
            for (int j = 0; j < 8; j++) br[j] = Bs[kk][colBase + j];
            #pragma unroll
            for (int i = 0; i < 8; i++)
                #pragma unroll
                for (int j = 0; j < 8; j++)
                    acc[i][j] = fmaf(ar[i], br[j], acc[i][j]);
        }
        __syncthreads();
        Aptr += BK;
        Bptr += (size_t)BK * N;
    }

    #pragma unroll
    for (int i = 0; i < 8; i++) {
        size_t row = (size_t)(bm + rowBase + i) * N + bn + colBase;
        #pragma unroll
        for (int j = 0; j < 8; j++) {
            float val = acc[i][j] * alpha;
            if (bias) val += bias[bn + colBase + j];
            if (accum) val += Cm[row + j];
            Cm[row + j] = val;
        }
    }
}

// NT: C[M,N] = alpha * A[M,K](row) * B[N,K](row)^T
__global__ void __launch_bounds__(256)
sgemm_nt(const float* __restrict__ A, const float* __restrict__ Bm,
         float* __restrict__ Cm,
         int M, int N, int K,
         size_t strideA, size_t strideB, size_t strideC,
         float alpha) {
    const int BM = 128, BN = 128, BK = 8;
    __shared__ float As[BK][BM];
    __shared__ float Bs[BK][BN];
    A  += (size_t)blockIdx.z * strideA;
    Bm += (size_t)blockIdx.z * strideB;
    Cm += (size_t)blockIdx.z * strideC;
    int bm = blockIdx.y * BM, bn = blockIdx.x * BN;
    int tid = threadIdx.x;

    const int am = tid >> 1, ak = (tid & 1) * 4;
    const float* Aptr = A  + (size_t)(bm + am) * K + ak;
    const float* Bptr = Bm + (size_t)(bn + am) * K + ak;

    const int rowBase = (tid >> 4) * 8;
    const int colBase = (tid & 15) * 8;

    float acc[8][8];
    #pragma unroll
    for (int i = 0; i < 8; i++)
        #pragma unroll
        for (int j = 0; j < 8; j++) acc[i][j] = 0.f;

    for (int k0 = 0; k0 < K; k0 += BK) {
        float4 a = *(const float4*)Aptr;
        float4 b = *(const float4*)Bptr;
        As[ak+0][am] = a.x; As[ak+1][am] = a.y; As[ak+2][am] = a.z; As[ak+3][am] = a.w;
        Bs[ak+0][am] = b.x; Bs[ak+1][am] = b.y; Bs[ak+2][am] = b.z; Bs[ak+3][am] = b.w;
        __syncthreads();
        #pragma unroll
        for (int kk = 0; kk < BK; ++kk) {
            float ar[8], br[8];
            #pragma unroll
            for (int i = 0; i < 8; i++) ar[i] = As[kk][rowBase + i];
            #pragma unroll
            for (int j = 0; j < 8; j++) br[j] = Bs[kk][colBase + j];
            #pragma unroll
            for (int i = 0; i < 8; i++)
                #pragma unroll
                for (int j = 0; j < 8; j++)
                    acc[i][j] = fmaf(ar[i], br[j], acc[i][j]);
        }
        __syncthreads();
        Aptr += BK;
        Bptr += BK;
    }

    #pragma unroll
    for (int i = 0; i < 8; i++) {
        size_t row = (size_t)(bm + rowBase + i) * N + bn + colBase;
        #pragma unroll
        for (int j = 0; j < 8; j++)
            Cm[row + j] = acc[i][j] * alpha;
    }
}

// ---------------- softmax (row-wise, 4096 per row) --------------------------
__global__ void __launch_bounds__(256)
softmax_kernel(float* __restrict__ attn) {
    float* row = attn + (size_t)blockIdx.x * SS;
    int t = threadIdx.x;
    __shared__ float sred[8];

    float v[16];
    float mx = -1e30f;
    #pragma unroll
    for (int i = 0; i < 16; i++) {
        v[i] = row[t + i * 256];
        mx = fmaxf(mx, v[i]);
    }
    #pragma unroll
    for (int o = 16; o > 0; o >>= 1) mx = fmaxf(mx, __shfl_xor_sync(0xffffffffu, mx, o));
    if ((t & 31) == 0) sred[t >> 5] = mx;
    __syncthreads();
    if (t == 0) {
        float m = sred[0];
        #pragma unroll
        for (int w = 1; w < 8; w++) m = fmaxf(m, sred[w]);
        sred[0] = m;
    }
    __syncthreads();
    mx = sred[0];
    __syncthreads();

    float sum = 0.f;
    #pragma unroll
    for (int i = 0; i < 16; i++) {
        v[i] = expf(v[i] - mx);
        sum += v[i];
    }
    #pragma unroll
    for (int o = 16; o > 0; o >>= 1) sum += __shfl_xor_sync(0xffffffffu, sum, o);
    if ((t & 31) == 0) sred[t >> 5] = sum;
    __syncthreads();
    if (t == 0) {
        float s = 0.f;
        #pragma unroll
        for (int w = 0; w < 8; w++) s += sred[w];
        sred[0] = s;
    }
    __syncthreads();
    float inv = 1.f / sred[0];

    #pragma unroll
    for (int i = 0; i < 16; i++)
        row[t + i * 256] = v[i] * inv;
}

// ---------------- launch -----------------------------------------------------
extern "C" void kernel_launch(void* const* d_in, const int* in_sizes, int n_in,
                              void* d_out, int out_size) {
    const float* x     = (const float*)d_in[0];
    const float* gamma = (const float*)d_in[1];
    const float* beta  = (const float*)d_in[2];
    const float* Wq    = (const float*)d_in[3];
    const float* bq    = (const float*)d_in[4];
    const float* Wk    = (const float*)d_in[5];
    const float* bk    = (const float*)d_in[6];
    const float* Wv    = (const float*)d_in[7];
    const float* bv    = (const float*)d_in[8];
    const float* Wp    = (const float*)d_in[9];
    const float* bp    = (const float*)d_in[10];
    float* out = (float*)d_out;

    // CRITICAL: resolve REAL device addresses of the __device__ scratch arrays.
    // Passing the symbols directly from host code passes the host shadow
    // address, which GB300's ATS happily dereferences (reading zeros from
    // host RAM) instead of faulting.
    float *p_xn, *p_q, *p_k, *p_v, *p_p, *p_attn;
    cudaGetSymbolAddress((void**)&p_xn,   g_xn);
    cudaGetSymbolAddress((void**)&p_q,    g_q);
    cudaGetSymbolAddress((void**)&p_k,    g_k);
    cudaGetSymbolAddress((void**)&p_v,    g_v);
    cudaGetSymbolAddress((void**)&p_p,    g_p);
    cudaGetSymbolAddress((void**)&p_attn, g_attn);

    const size_t SC  = (size_t)SS * CC;   // per-batch q/k/v stride
    const size_t SS2 = (size_t)SS * SS;   // per-batch attn stride
    const float scale = 0.044194173824159216f; // 512^-0.5

    // 1) instance-norm stats (fp64)
    zero_stats_kernel<<<(NB * CC + 511) / 512, 512>>>();
    stats_kernel<<<dim3(NB, 32), 512>>>(x);
    finalize_stats_kernel<<<(NB * CC + 511) / 512, 512>>>();

    // 2) normalize -> g_xn, and d_out (residual base)
    {
        size_t n4 = (size_t)NB * SS * CC / 4;
        norm_kernel<<<(unsigned)((n4 + 255) / 256), 256>>>(x, gamma, beta, p_xn, out);
    }

    // 3) q, k, v projections: [32768,512] @ [512,512] + bias
    {
        dim3 grid(CC / 128, (NB * SS) / 128, 1);
        sgemm_nn<<<grid, 256>>>(p_xn, Wq, bq, p_q, NB * SS, CC, CC, 0, 0, 0, 1.f, 0);
        sgemm_nn<<<grid, 256>>>(p_xn, Wk, bk, p_k, NB * SS, CC, CC, 0, 0, 0, 1.f, 0);
        sgemm_nn<<<grid, 256>>>(p_xn, Wv, bv, p_v, NB * SS, CC, CC, 0, 0, 0, 1.f, 0);
    }

    // 4) scores = scale * q @ k^T  (per batch, NT)
    {
        dim3 grid(SS / 128, SS / 128, NB);
        sgemm_nt<<<grid, 256>>>(p_q, p_k, p_attn, SS, SS, CC, SC, SC, SS2, scale);
    }

    // 5) softmax over last dim
    softmax_kernel<<<NB * SS, 256>>>(p_attn);

    // 6) proj = attn @ v (per batch, NN, K=4096)
    {
        dim3 grid(CC / 128, SS / 128, NB);
        sgemm_nn<<<grid, 256>>>(p_attn, p_v, nullptr, p_p, SS, CC, SS, SS2, SC, SC, 1.f, 0);
    }

    // 7) out = xn (already in d_out) + proj @ Wp + bp
    {
        dim3 grid(CC / 128, (NB * SS) / 128, 1);
        sgemm_nn<<<grid, 256>>>(p_p, Wp, bp, out, NB * SS, CC, CC, 0, 0, 0, 1.f, 1);
    }
}